// round 1
// baseline (speedup 1.0000x reference)
#include <cuda_runtime.h>
#include <math.h>
#include <stdint.h>

// Problem constants (fixed by the dataset)
#define T_TOK 1024
#define HID   1024
#define NE    8
#define INTER 2048
#define TOPK  2
#define NROWS (T_TOK * TOPK)   // 2048 routed (token, expert) rows

// GEMM tiling
#define BM 128
#define BN 64
#define BK 16

// ---------------------------------------------------------------------------
// Scratch (device globals: allocation inside kernel_launch is forbidden)
// ---------------------------------------------------------------------------
__device__ int   g_sorted[NROWS];          // expert-sorted row -> token id
__device__ int   g_inv[NROWS];             // (token, k) -> expert-sorted row
__device__ float g_w[NROWS];               // (token, k) -> normalized weight
__device__ int   g_off[NE];                // expert row offsets
__device__ int   g_cnt[NE];                // expert row counts
__device__ float g_act[(size_t)NROWS * INTER];   // silu(gate)*up   (16.8 MB)
__device__ float g_down[(size_t)NROWS * HID];    // down proj rows  ( 8.4 MB)

// ---------------------------------------------------------------------------
// 1) Router: softmax -> top-2 -> normalize -> sort rows by expert
//    One block, 1024 threads (one per token).
// ---------------------------------------------------------------------------
__global__ void router_kernel(const float* __restrict__ logits) {
    int t = threadIdx.x;
    __shared__ int s_cnt[NE];
    __shared__ int s_off[NE];
    __shared__ int s_pos[NE];
    if (t < NE) { s_cnt[t] = 0; s_pos[t] = 0; }
    __syncthreads();

    float v[NE];
    float mx = -1e30f;
#pragma unroll
    for (int e = 0; e < NE; e++) {
        v[e] = logits[t * NE + e];
        mx = fmaxf(mx, v[e]);
    }
#pragma unroll
    for (int e = 0; e < NE; e++) v[e] = expf(v[e] - mx);

    // top-1 (strict > keeps lowest index on ties, matching jax.lax.top_k)
    int i0 = 0;
#pragma unroll
    for (int e = 1; e < NE; e++) if (v[e] > v[i0]) i0 = e;
    // top-2
    int i1 = (i0 == 0) ? 1 : 0;
#pragma unroll
    for (int e = 0; e < NE; e++) if (e != i0 && v[e] > v[i1]) i1 = e;

    float s  = v[i0] + v[i1];       // softmax denom cancels in the ratio
    g_w[t * 2 + 0] = v[i0] / s;
    g_w[t * 2 + 1] = v[i1] / s;

    atomicAdd(&s_cnt[i0], 1);
    atomicAdd(&s_cnt[i1], 1);
    __syncthreads();

    if (t == 0) {
        int acc = 0;
#pragma unroll
        for (int e = 0; e < NE; e++) {
            s_off[e] = acc;
            g_off[e] = acc;
            g_cnt[e] = s_cnt[e];
            acc += s_cnt[e];
        }
    }
    __syncthreads();

    int p0 = s_off[i0] + atomicAdd(&s_pos[i0], 1);
    g_sorted[p0]   = t;
    g_inv[t * 2]   = p0;
    int p1 = s_off[i1] + atomicAdd(&s_pos[i1], 1);
    g_sorted[p1]     = t;
    g_inv[t * 2 + 1] = p1;
}

// ---------------------------------------------------------------------------
// 2) Gate+Up GEMM with fused SiLU epilogue.
//    Per expert e: act[m, n] = silu(x[m] . w13[e, n]) * (x[m] . w13[e, I+n])
//    grid = (INTER/BN, ceil(T/BM), NE), 256 threads, 8x4 register tile.
// ---------------------------------------------------------------------------
__global__ void __launch_bounds__(256, 2)
gateup_kernel(const float* __restrict__ hidden, const float* __restrict__ w13) {
    int e   = blockIdx.z;
    int cnt = g_cnt[e];
    int m0  = blockIdx.y * BM;
    if (m0 >= cnt) return;
    int off = g_off[e];
    int n0  = blockIdx.x * BN;
    int tid = threadIdx.x;

    __shared__ float sA [BK][BM];
    __shared__ float sBg[BK][BN];
    __shared__ float sBu[BK][BN];
    __shared__ int   s_tok[BM];

    if (tid < BM) {
        int m = m0 + tid;
        s_tok[tid] = (m < cnt) ? g_sorted[off + m] : g_sorted[off];  // pad w/ valid row
    }
    __syncthreads();

    int tx = tid & 15;        // n-tile: 4 outputs at tx*4
    int ty = tid >> 4;        // m-tile: 8 outputs at ty*8

    float acc_g[8][4];
    float acc_u[8][4];
#pragma unroll
    for (int i = 0; i < 8; i++)
#pragma unroll
        for (int j = 0; j < 4; j++) { acc_g[i][j] = 0.f; acc_u[i][j] = 0.f; }

    const float* wg = w13 + ((size_t)e * 2 * INTER + n0) * HID;
    const float* wu = w13 + ((size_t)e * 2 * INTER + INTER + n0) * HID;

    int brow = tid >> 2;      // B: 64 rows x 4 float4
    int bc4  = tid & 3;

    for (int k0 = 0; k0 < HID; k0 += BK) {
        // A tile: 128 rows x 16 cols, gathered by token; 2 float4 per thread
#pragma unroll
        for (int i = 0; i < 2; i++) {
            int lin = tid + i * 256;
            int row = lin >> 2, c4 = lin & 3;
            float4 a = *(const float4*)(hidden + (size_t)s_tok[row] * HID + k0 + c4 * 4);
            sA[c4 * 4 + 0][row] = a.x;
            sA[c4 * 4 + 1][row] = a.y;
            sA[c4 * 4 + 2][row] = a.z;
            sA[c4 * 4 + 3][row] = a.w;
        }
        // B tiles (gate + up): 64 rows x 16 cols each; 1 float4 per thread each
        {
            float4 bg = *(const float4*)(wg + (size_t)brow * HID + k0 + bc4 * 4);
            sBg[bc4 * 4 + 0][brow] = bg.x;
            sBg[bc4 * 4 + 1][brow] = bg.y;
            sBg[bc4 * 4 + 2][brow] = bg.z;
            sBg[bc4 * 4 + 3][brow] = bg.w;
            float4 bu = *(const float4*)(wu + (size_t)brow * HID + k0 + bc4 * 4);
            sBu[bc4 * 4 + 0][brow] = bu.x;
            sBu[bc4 * 4 + 1][brow] = bu.y;
            sBu[bc4 * 4 + 2][brow] = bu.z;
            sBu[bc4 * 4 + 3][brow] = bu.w;
        }
        __syncthreads();

#pragma unroll
        for (int k = 0; k < BK; k++) {
            float4 a0 = *(const float4*)&sA [k][ty * 8];
            float4 a1 = *(const float4*)&sA [k][ty * 8 + 4];
            float4 bg = *(const float4*)&sBg[k][tx * 4];
            float4 bu = *(const float4*)&sBu[k][tx * 4];
            float am[8] = {a0.x, a0.y, a0.z, a0.w, a1.x, a1.y, a1.z, a1.w};
            float gv[4] = {bg.x, bg.y, bg.z, bg.w};
            float uv[4] = {bu.x, bu.y, bu.z, bu.w};
#pragma unroll
            for (int mi = 0; mi < 8; mi++)
#pragma unroll
                for (int ni = 0; ni < 4; ni++) {
                    acc_g[mi][ni] = fmaf(am[mi], gv[ni], acc_g[mi][ni]);
                    acc_u[mi][ni] = fmaf(am[mi], uv[ni], acc_u[mi][ni]);
                }
        }
        __syncthreads();
    }

    // Epilogue: silu(gate) * up -> g_act
#pragma unroll
    for (int mi = 0; mi < 8; mi++) {
        int m = m0 + ty * 8 + mi;
        if (m < cnt) {
            float4 r;
            float g0 = acc_g[mi][0], g1 = acc_g[mi][1], g2 = acc_g[mi][2], g3 = acc_g[mi][3];
            r.x = (g0 / (1.f + expf(-g0))) * acc_u[mi][0];
            r.y = (g1 / (1.f + expf(-g1))) * acc_u[mi][1];
            r.z = (g2 / (1.f + expf(-g2))) * acc_u[mi][2];
            r.w = (g3 / (1.f + expf(-g3))) * acc_u[mi][3];
            *(float4*)(g_act + (size_t)(off + m) * INTER + n0 + tx * 4) = r;
        }
    }
}

// ---------------------------------------------------------------------------
// 3) Down GEMM: down[m, h] = act[m] . w2[e, h, :]
//    grid = (HID/BN, ceil(T/BM), NE), 256 threads, 8x4 register tile.
// ---------------------------------------------------------------------------
__global__ void __launch_bounds__(256, 2)
down_kernel(const float* __restrict__ w2) {
    int e   = blockIdx.z;
    int cnt = g_cnt[e];
    int m0  = blockIdx.y * BM;
    if (m0 >= cnt) return;
    int off = g_off[e];
    int n0  = blockIdx.x * BN;
    int tid = threadIdx.x;

    __shared__ float sA[BK][BM];
    __shared__ float sB[BK][BN];

    int tx = tid & 15;
    int ty = tid >> 4;

    float acc[8][4];
#pragma unroll
    for (int i = 0; i < 8; i++)
#pragma unroll
        for (int j = 0; j < 4; j++) acc[i][j] = 0.f;

    const float* wp = w2 + ((size_t)e * HID + n0) * INTER;

    int brow = tid >> 2;
    int bc4  = tid & 3;

    for (int k0 = 0; k0 < INTER; k0 += BK) {
        // A tile from g_act (contiguous rows; clamp padded rows into bounds)
#pragma unroll
        for (int i = 0; i < 2; i++) {
            int lin = tid + i * 256;
            int row = lin >> 2, c4 = lin & 3;
            int m   = m0 + row;
            int gr  = off + ((m < cnt) ? m : 0);
            float4 a = *(const float4*)(g_act + (size_t)gr * INTER + k0 + c4 * 4);
            sA[c4 * 4 + 0][row] = a.x;
            sA[c4 * 4 + 1][row] = a.y;
            sA[c4 * 4 + 2][row] = a.z;
            sA[c4 * 4 + 3][row] = a.w;
        }
        {
            float4 b = *(const float4*)(wp + (size_t)brow * INTER + k0 + bc4 * 4);
            sB[bc4 * 4 + 0][brow] = b.x;
            sB[bc4 * 4 + 1][brow] = b.y;
            sB[bc4 * 4 + 2][brow] = b.z;
            sB[bc4 * 4 + 3][brow] = b.w;
        }
        __syncthreads();

#pragma unroll
        for (int k = 0; k < BK; k++) {
            float4 a0 = *(const float4*)&sA[k][ty * 8];
            float4 a1 = *(const float4*)&sA[k][ty * 8 + 4];
            float4 b  = *(const float4*)&sB[k][tx * 4];
            float am[8] = {a0.x, a0.y, a0.z, a0.w, a1.x, a1.y, a1.z, a1.w};
            float bv[4] = {b.x, b.y, b.z, b.w};
#pragma unroll
            for (int mi = 0; mi < 8; mi++)
#pragma unroll
                for (int ni = 0; ni < 4; ni++)
                    acc[mi][ni] = fmaf(am[mi], bv[ni], acc[mi][ni]);
        }
        __syncthreads();
    }

#pragma unroll
    for (int mi = 0; mi < 8; mi++) {
        int m = m0 + ty * 8 + mi;
        if (m < cnt) {
            float4 r = {acc[mi][0], acc[mi][1], acc[mi][2], acc[mi][3]};
            *(float4*)(g_down + (size_t)(off + m) * HID + n0 + tx * 4) = r;
        }
    }
}

// ---------------------------------------------------------------------------
// 4) Combine: out[t] = w0 * down[row(t,0)] + w1 * down[row(t,1)]
//    grid = T_TOK blocks x 256 threads (float4 over H=1024)
// ---------------------------------------------------------------------------
__global__ void combine_kernel(float* __restrict__ out) {
    int t  = blockIdx.x;
    float w0 = g_w[t * 2 + 0];
    float w1 = g_w[t * 2 + 1];
    const float* d0 = g_down + (size_t)g_inv[t * 2 + 0] * HID;
    const float* d1 = g_down + (size_t)g_inv[t * 2 + 1] * HID;
    int h = threadIdx.x * 4;
    float4 a = *(const float4*)(d0 + h);
    float4 b = *(const float4*)(d1 + h);
    float4 r;
    r.x = w0 * a.x + w1 * b.x;
    r.y = w0 * a.y + w1 * b.y;
    r.z = w0 * a.z + w1 * b.z;
    r.w = w0 * a.w + w1 * b.w;
    *(float4*)(out + (size_t)t * HID + h) = r;
}

// ---------------------------------------------------------------------------
// Launch
// ---------------------------------------------------------------------------
extern "C" void kernel_launch(void* const* d_in, const int* in_sizes, int n_in,
                              void* d_out, int out_size) {
    const float* hidden = (const float*)d_in[0];
    const float* logits = (const float*)d_in[1];
    const float* w13    = (const float*)d_in[2];
    const float* w2     = (const float*)d_in[3];
    float* out = (float*)d_out;

    router_kernel<<<1, T_TOK>>>(logits);

    dim3 gup(INTER / BN, (T_TOK + BM - 1) / BM, NE);   // 32 x 8 x 8
    gateup_kernel<<<gup, 256>>>(hidden, w13);

    dim3 gdn(HID / BN, (T_TOK + BM - 1) / BM, NE);     // 16 x 8 x 8
    down_kernel<<<gdn, 256>>>(w2);

    combine_kernel<<<T_TOK, 256>>>(out);
}

// round 6
// speedup vs baseline: 2.3379x; 2.3379x over previous
#include <cuda_runtime.h>
#include <math.h>
#include <stdint.h>

// Problem constants
#define T_TOK 1024
#define HID   1024
#define NE    8
#define INTER 2048
#define NROWS (T_TOK * 2)

// ---------------------------------------------------------------------------
// Scratch
// ---------------------------------------------------------------------------
__device__ int   g_sorted[NROWS];
__device__ int   g_inv[NROWS];
__device__ float g_w[NROWS];
__device__ int   g_off[NE];
__device__ int   g_cnt[NE];
__device__ float g_act[(size_t)NROWS * INTER];
__device__ float g_down[(size_t)NROWS * HID];

// ---------------------------------------------------------------------------
// Helpers: mma.sync bf16 path (plain sm_100 — no tcgen05 on this target)
// ---------------------------------------------------------------------------
__device__ __forceinline__ uint32_t smem_u32(const void* p) {
    uint32_t a;
    asm("{ .reg .u64 t; cvta.to.shared.u64 t, %1; cvt.u32.u64 %0, t; }" : "=r"(a) : "l"(p));
    return a;
}
__device__ __forceinline__ void ldmx4(uint32_t r[4], uint32_t addr) {
    asm volatile("ldmatrix.sync.aligned.m8n8.x4.shared.b16 {%0,%1,%2,%3}, [%4];"
                 : "=r"(r[0]), "=r"(r[1]), "=r"(r[2]), "=r"(r[3]) : "r"(addr));
}
__device__ __forceinline__ void mma16816(float c[4], const uint32_t a[4],
                                         uint32_t b0, uint32_t b1) {
    asm volatile(
        "mma.sync.aligned.m16n8k16.row.col.f32.bf16.bf16.f32 "
        "{%0,%1,%2,%3}, {%4,%5,%6,%7}, {%8,%9}, {%0,%1,%2,%3};"
        : "+f"(c[0]), "+f"(c[1]), "+f"(c[2]), "+f"(c[3])
        : "r"(a[0]), "r"(a[1]), "r"(a[2]), "r"(a[3]), "r"(b0), "r"(b1));
}
// fp32 pair -> bf16x2 hi (RN) + bf16x2 lo (residual, RN). lo halfword = x0.
__device__ __forceinline__ void split2(float x0, float x1, uint32_t& h, uint32_t& l) {
    uint32_t hb;
    asm("cvt.rn.bf16x2.f32 %0, %1, %2;" : "=r"(hb) : "f"(x1), "f"(x0));
    float h0 = __uint_as_float(hb << 16);
    float h1 = __uint_as_float(hb & 0xFFFF0000u);
    float l0 = x0 - h0;
    float l1 = x1 - h1;
    asm("cvt.rn.bf16x2.f32 %0, %1, %2;" : "=r"(l) : "f"(l1), "f"(l0));
    h = hb;
}
__device__ __forceinline__ void sts_v2(uint32_t addr, uint32_t a, uint32_t b) {
    asm volatile("st.shared.v2.b32 [%0], {%1,%2};" :: "r"(addr), "r"(a), "r"(b) : "memory");
}
// Convert one float4 (4 consecutive k) into 4 bf16 hi + 4 bf16 lo, store 8B each.
__device__ __forceinline__ void conv_store(uint32_t sh, uint32_t sl,
                                           int row, int kq, float4 v) {
    uint32_t h0, h1, l0, l1;
    split2(v.x, v.y, h0, l0);
    split2(v.z, v.w, h1, l1);
    uint32_t o = (uint32_t)(row * 40 + kq * 4) * 2;   // stride 40 bf16 per row
    sts_v2(sh + o, h0, h1);
    sts_v2(sl + o, l0, l1);
}

// ldmatrix address builders (stride 40 bf16 = 80B rows; conflict-free)
__device__ __forceinline__ uint32_t addrA(uint32_t base, int rowBase, int k, int lane) {
    int row = rowBase + (lane & 15);
    int col = k + 8 * (lane >> 4);
    return base + (uint32_t)(row * 40 + col) * 2;
}
__device__ __forceinline__ uint32_t addrB(uint32_t base, int nBase, int k, int lane) {
    int n = nBase + (lane & 7) + 8 * (lane >> 4);
    int kk = k + 8 * ((lane >> 3) & 1);
    return base + (uint32_t)(n * 40 + kk) * 2;
}

// ---------------------------------------------------------------------------
// 1) Router
// ---------------------------------------------------------------------------
__global__ void router_kernel(const float* __restrict__ logits) {
    int t = threadIdx.x;
    __shared__ int s_cnt[NE];
    __shared__ int s_off[NE];
    __shared__ int s_pos[NE];
    if (t < NE) { s_cnt[t] = 0; s_pos[t] = 0; }
    __syncthreads();

    float v[NE];
    float mx = -1e30f;
#pragma unroll
    for (int e = 0; e < NE; e++) { v[e] = logits[t * NE + e]; mx = fmaxf(mx, v[e]); }
#pragma unroll
    for (int e = 0; e < NE; e++) v[e] = expf(v[e] - mx);

    int i0 = 0;
#pragma unroll
    for (int e = 1; e < NE; e++) if (v[e] > v[i0]) i0 = e;
    int i1 = (i0 == 0) ? 1 : 0;
#pragma unroll
    for (int e = 0; e < NE; e++) if (e != i0 && v[e] > v[i1]) i1 = e;

    float s = v[i0] + v[i1];
    g_w[t * 2 + 0] = v[i0] / s;
    g_w[t * 2 + 1] = v[i1] / s;

    atomicAdd(&s_cnt[i0], 1);
    atomicAdd(&s_cnt[i1], 1);
    __syncthreads();
    if (t == 0) {
        int acc = 0;
#pragma unroll
        for (int e = 0; e < NE; e++) {
            s_off[e] = acc; g_off[e] = acc; g_cnt[e] = s_cnt[e]; acc += s_cnt[e];
        }
    }
    __syncthreads();
    int p0 = s_off[i0] + atomicAdd(&s_pos[i0], 1);
    g_sorted[p0] = t;  g_inv[t * 2] = p0;
    int p1 = s_off[i1] + atomicAdd(&s_pos[i1], 1);
    g_sorted[p1] = t;  g_inv[t * 2 + 1] = p1;
}

// ---------------------------------------------------------------------------
// 2) Gate+Up GEMM, mma.sync bf16, triple split. CTA: M=128, 64 gate + 64 up
//    cols, BK=32. 8 warps (4 M x 2 N), warp tile 32x32 per operand.
// ---------------------------------------------------------------------------
__global__ void __launch_bounds__(256)
gateup_mma(const float* __restrict__ hidden, const float* __restrict__ w13) {
    int e   = blockIdx.z;
    int cnt = g_cnt[e];
    int m0  = blockIdx.y * 128;
    if (m0 >= cnt) return;
    int off = g_off[e];
    int n0  = blockIdx.x * 64;
    int tid  = threadIdx.x;
    int wid  = tid >> 5, lane = tid & 31;
    int wm   = wid & 3, wn = wid >> 2;      // 4 x 2 warp grid

    __shared__ __align__(16) int      s_tok[128];
    __shared__ __align__(16) uint16_t sAh[128 * 40];
    __shared__ __align__(16) uint16_t sAl[128 * 40];
    __shared__ __align__(16) uint16_t sBgh[64 * 40];
    __shared__ __align__(16) uint16_t sBgl[64 * 40];
    __shared__ __align__(16) uint16_t sBuh[64 * 40];
    __shared__ __align__(16) uint16_t sBul[64 * 40];

    uint32_t uAh = smem_u32(sAh),  uAl = smem_u32(sAl);
    uint32_t uBgh = smem_u32(sBgh), uBgl = smem_u32(sBgl);
    uint32_t uBuh = smem_u32(sBuh), uBul = smem_u32(sBul);

    if (tid < 128) {
        int m = m0 + tid;
        s_tok[tid] = (m < cnt) ? g_sorted[off + m] : g_sorted[off];
    }
    __syncthreads();

    const float* wg = w13 + ((size_t)e * 2 * INTER + n0) * HID;
    const float* wu = w13 + ((size_t)e * 2 * INTER + INTER + n0) * HID;

    float accg[2][4][4];
    float accu[2][4][4];
#pragma unroll
    for (int i = 0; i < 2; i++)
#pragma unroll
        for (int j = 0; j < 4; j++)
#pragma unroll
            for (int r = 0; r < 4; r++) { accg[i][j][r] = 0.f; accu[i][j][r] = 0.f; }

    // staging registers for next chunk
    float4 stA[4], stBg[2], stBu[2];
    int rowA[4], kqA[4], rowB[2], kqB[2];
#pragma unroll
    for (int i = 0; i < 4; i++) { int u = tid + i * 256; rowA[i] = u >> 3; kqA[i] = u & 7; }
#pragma unroll
    for (int i = 0; i < 2; i++) { int u = tid + i * 256; rowB[i] = u >> 3; kqB[i] = u & 7; }

#define GU_LOAD(k0)                                                                     \
    do {                                                                                \
        _Pragma("unroll")                                                               \
        for (int i = 0; i < 4; i++)                                                     \
            stA[i] = *(const float4*)(hidden + (size_t)s_tok[rowA[i]] * HID + (k0) + kqA[i] * 4); \
        _Pragma("unroll")                                                               \
        for (int i = 0; i < 2; i++) {                                                   \
            stBg[i] = *(const float4*)(wg + (size_t)rowB[i] * HID + (k0) + kqB[i] * 4); \
            stBu[i] = *(const float4*)(wu + (size_t)rowB[i] * HID + (k0) + kqB[i] * 4); \
        }                                                                               \
    } while (0)

#define GU_STORE()                                                                      \
    do {                                                                                \
        _Pragma("unroll")                                                               \
        for (int i = 0; i < 4; i++) conv_store(uAh, uAl, rowA[i], kqA[i], stA[i]);      \
        _Pragma("unroll")                                                               \
        for (int i = 0; i < 2; i++) {                                                   \
            conv_store(uBgh, uBgl, rowB[i], kqB[i], stBg[i]);                           \
            conv_store(uBuh, uBul, rowB[i], kqB[i], stBu[i]);                           \
        }                                                                               \
    } while (0)

    GU_LOAD(0);
    GU_STORE();
    __syncthreads();

    const int NCH = HID / 32;
    for (int ch = 0; ch < NCH; ch++) {
        if (ch + 1 < NCH) GU_LOAD((ch + 1) * 32);

#pragma unroll
        for (int ks = 0; ks < 2; ks++) {
            int k = ks * 16;
            uint32_t ah[2][4], al[2][4];
#pragma unroll
            for (int mt = 0; mt < 2; mt++) {
                ldmx4(ah[mt], addrA(uAh, wm * 32 + mt * 16, k, lane));
                ldmx4(al[mt], addrA(uAl, wm * 32 + mt * 16, k, lane));
            }
            uint32_t bgh[2][4], bgl[2][4], buh[2][4], bul[2][4];
#pragma unroll
            for (int bt = 0; bt < 2; bt++) {
                int nb = wn * 32 + bt * 16;
                ldmx4(bgh[bt], addrB(uBgh, nb, k, lane));
                ldmx4(bgl[bt], addrB(uBgl, nb, k, lane));
                ldmx4(buh[bt], addrB(uBuh, nb, k, lane));
                ldmx4(bul[bt], addrB(uBul, nb, k, lane));
            }
#pragma unroll
            for (int mt = 0; mt < 2; mt++) {
#pragma unroll
                for (int bt = 0; bt < 2; bt++) {
#pragma unroll
                    for (int s = 0; s < 2; s++) {   // n8 sub-tile within x4
                        int nt = bt * 2 + s;
                        uint32_t g0 = bgh[bt][s * 2], g1 = bgh[bt][s * 2 + 1];
                        uint32_t gl0 = bgl[bt][s * 2], gl1 = bgl[bt][s * 2 + 1];
                        uint32_t u0 = buh[bt][s * 2], u1 = buh[bt][s * 2 + 1];
                        uint32_t ul0 = bul[bt][s * 2], ul1 = bul[bt][s * 2 + 1];
                        mma16816(accg[mt][nt], ah[mt], g0, g1);
                        mma16816(accg[mt][nt], ah[mt], gl0, gl1);
                        mma16816(accg[mt][nt], al[mt], g0, g1);
                        mma16816(accu[mt][nt], ah[mt], u0, u1);
                        mma16816(accu[mt][nt], ah[mt], ul0, ul1);
                        mma16816(accu[mt][nt], al[mt], u0, u1);
                    }
                }
            }
        }
        __syncthreads();
        if (ch + 1 < NCH) {
            GU_STORE();
            __syncthreads();
        }
    }

    // Epilogue: silu(gate)*up -> g_act
    int qr = lane >> 2, qc = (lane & 3) * 2;
#pragma unroll
    for (int mt = 0; mt < 2; mt++) {
#pragma unroll
        for (int nt = 0; nt < 4; nt++) {
            int col = n0 + wn * 32 + nt * 8 + qc;
#pragma unroll
            for (int half = 0; half < 2; half++) {
                int m = m0 + wm * 32 + mt * 16 + qr + half * 8;
                if (m < cnt) {
                    float gv0 = accg[mt][nt][half * 2],     uv0 = accu[mt][nt][half * 2];
                    float gv1 = accg[mt][nt][half * 2 + 1], uv1 = accu[mt][nt][half * 2 + 1];
                    float2 r;
                    r.x = (gv0 / (1.f + expf(-gv0))) * uv0;
                    r.y = (gv1 / (1.f + expf(-gv1))) * uv1;
                    *(float2*)(g_act + (size_t)(off + m) * INTER + col) = r;
                }
            }
        }
    }
#undef GU_LOAD
#undef GU_STORE
}

// ---------------------------------------------------------------------------
// 3) Down GEMM, mma.sync bf16, triple split. CTA: M=128, N=128, BK=32.
//    8 warps (4 M x 2 N), warp tile 32x64.
// ---------------------------------------------------------------------------
__global__ void __launch_bounds__(256)
down_mma(const float* __restrict__ w2) {
    int e   = blockIdx.z;
    int cnt = g_cnt[e];
    int m0  = blockIdx.y * 128;
    if (m0 >= cnt) return;
    int off = g_off[e];
    int n0  = blockIdx.x * 128;
    int tid  = threadIdx.x;
    int wid  = tid >> 5, lane = tid & 31;
    int wm   = wid & 3, wn = wid >> 2;

    __shared__ __align__(16) uint16_t sAh[128 * 40];
    __shared__ __align__(16) uint16_t sAl[128 * 40];
    __shared__ __align__(16) uint16_t sBh[128 * 40];
    __shared__ __align__(16) uint16_t sBl[128 * 40];

    uint32_t uAh = smem_u32(sAh), uAl = smem_u32(sAl);
    uint32_t uBh = smem_u32(sBh), uBl = smem_u32(sBl);

    const float* wp = w2 + ((size_t)e * HID + n0) * INTER;

    float acc[2][8][4];
#pragma unroll
    for (int i = 0; i < 2; i++)
#pragma unroll
        for (int j = 0; j < 8; j++)
#pragma unroll
            for (int r = 0; r < 4; r++) acc[i][j][r] = 0.f;

    float4 stA[4], stB[4];
    int rowU[4], kqU[4];
#pragma unroll
    for (int i = 0; i < 4; i++) { int u = tid + i * 256; rowU[i] = u >> 3; kqU[i] = u & 7; }

#define DN_LOAD(k0)                                                                     \
    do {                                                                                \
        _Pragma("unroll")                                                               \
        for (int i = 0; i < 4; i++) {                                                   \
            int m = m0 + rowU[i];                                                       \
            size_t gr = (size_t)(off + ((m < cnt) ? m : 0));                            \
            stA[i] = *(const float4*)(g_act + gr * INTER + (k0) + kqU[i] * 4);          \
            stB[i] = *(const float4*)(wp + (size_t)rowU[i] * INTER + (k0) + kqU[i] * 4);\
        }                                                                               \
    } while (0)

#define DN_STORE()                                                                      \
    do {                                                                                \
        _Pragma("unroll")                                                               \
        for (int i = 0; i < 4; i++) {                                                   \
            conv_store(uAh, uAl, rowU[i], kqU[i], stA[i]);                              \
            conv_store(uBh, uBl, rowU[i], kqU[i], stB[i]);                              \
        }                                                                               \
    } while (0)

    DN_LOAD(0);
    DN_STORE();
    __syncthreads();

    const int NCH = INTER / 32;
    for (int ch = 0; ch < NCH; ch++) {
        if (ch + 1 < NCH) DN_LOAD((ch + 1) * 32);

#pragma unroll
        for (int ks = 0; ks < 2; ks++) {
            int k = ks * 16;
            uint32_t ah[2][4], al[2][4];
#pragma unroll
            for (int mt = 0; mt < 2; mt++) {
                ldmx4(ah[mt], addrA(uAh, wm * 32 + mt * 16, k, lane));
                ldmx4(al[mt], addrA(uAl, wm * 32 + mt * 16, k, lane));
            }
            uint32_t bh[4][4], bl[4][4];
#pragma unroll
            for (int bt = 0; bt < 4; bt++) {
                int nb = wn * 64 + bt * 16;
                ldmx4(bh[bt], addrB(uBh, nb, k, lane));
                ldmx4(bl[bt], addrB(uBl, nb, k, lane));
            }
#pragma unroll
            for (int mt = 0; mt < 2; mt++) {
#pragma unroll
                for (int bt = 0; bt < 4; bt++) {
#pragma unroll
                    for (int s = 0; s < 2; s++) {
                        int nt = bt * 2 + s;
                        uint32_t b0 = bh[bt][s * 2], b1 = bh[bt][s * 2 + 1];
                        uint32_t c0 = bl[bt][s * 2], c1 = bl[bt][s * 2 + 1];
                        mma16816(acc[mt][nt], ah[mt], b0, b1);
                        mma16816(acc[mt][nt], ah[mt], c0, c1);
                        mma16816(acc[mt][nt], al[mt], b0, b1);
                    }
                }
            }
        }
        __syncthreads();
        if (ch + 1 < NCH) {
            DN_STORE();
            __syncthreads();
        }
    }

    int qr = lane >> 2, qc = (lane & 3) * 2;
#pragma unroll
    for (int mt = 0; mt < 2; mt++) {
#pragma unroll
        for (int nt = 0; nt < 8; nt++) {
            int col = n0 + wn * 64 + nt * 8 + qc;
#pragma unroll
            for (int half = 0; half < 2; half++) {
                int m = m0 + wm * 32 + mt * 16 + qr + half * 8;
                if (m < cnt) {
                    float2 r;
                    r.x = acc[mt][nt][half * 2];
                    r.y = acc[mt][nt][half * 2 + 1];
                    *(float2*)(g_down + (size_t)(off + m) * HID + col) = r;
                }
            }
        }
    }
#undef DN_LOAD
#undef DN_STORE
}

// ---------------------------------------------------------------------------
// 4) Combine
// ---------------------------------------------------------------------------
__global__ void combine_kernel(float* __restrict__ out) {
    int t = blockIdx.x;
    float w0 = g_w[t * 2 + 0];
    float w1 = g_w[t * 2 + 1];
    const float* d0 = g_down + (size_t)g_inv[t * 2 + 0] * HID;
    const float* d1 = g_down + (size_t)g_inv[t * 2 + 1] * HID;
    int h = threadIdx.x * 4;
    float4 a = *(const float4*)(d0 + h);
    float4 b = *(const float4*)(d1 + h);
    float4 r;
    r.x = w0 * a.x + w1 * b.x;
    r.y = w0 * a.y + w1 * b.y;
    r.z = w0 * a.z + w1 * b.z;
    r.w = w0 * a.w + w1 * b.w;
    *(float4*)(out + (size_t)t * HID + h) = r;
}

// ---------------------------------------------------------------------------
// Launch
// ---------------------------------------------------------------------------
extern "C" void kernel_launch(void* const* d_in, const int* in_sizes, int n_in,
                              void* d_out, int out_size) {
    const float* hidden = (const float*)d_in[0];
    const float* logits = (const float*)d_in[1];
    const float* w13    = (const float*)d_in[2];
    const float* w2     = (const float*)d_in[3];
    float* out = (float*)d_out;

    router_kernel<<<1, T_TOK>>>(logits);

    dim3 gup(INTER / 64, (T_TOK + 127) / 128, NE);   // 32 x 8 x 8
    gateup_mma<<<gup, 256>>>(hidden, w13);

    dim3 gdn(HID / 128, (T_TOK + 127) / 128, NE);    // 8 x 8 x 8
    down_mma<<<gdn, 256>>>(w2);

    combine_kernel<<<T_TOK, 256>>>(out);
}